// round 1
// baseline (speedup 1.0000x reference)
#include <cuda_runtime.h>
#include <math_constants.h>

#define NMAX 4096
#define WARPS_PER_BLOCK 8
#define BLOCK_THREADS (WARPS_PER_BLOCK * 32)

// strict-less insert (per-lane scan: within a lane j is ascending, so strict <
// keeps the earlier index on exact ties, matching top_k stability)
#define TRY_INSERT(d2v, jv)                                        \
    if ((d2v) < s3) {                                              \
        if ((d2v) < s1) {                                          \
            s3 = s2; i3 = i2; s2 = s1; i2 = i1;                    \
            if ((d2v) < s0) { s1 = s0; i1 = i0; s0 = (d2v); i0 = (jv); } \
            else            { s1 = (d2v); i1 = (jv); }             \
        } else {                                                   \
            if ((d2v) < s2) { s3 = s2; i3 = i2; s2 = (d2v); i2 = (jv); } \
            else            { s3 = (d2v); i3 = (jv); }             \
        }                                                          \
    }

// merge insert with index tie-break (cross-lane merge: interleaved j order,
// so equal distances must resolve to the smaller index)
#define LESSI(da, ja, db, jb) (((da) < (db)) || ((da) == (db) && (ja) < (jb)))
#define MERGE_INSERT(dv, jv)                                       \
    if (LESSI(dv, jv, s3, i3)) {                                   \
        if (LESSI(dv, jv, s1, i1)) {                               \
            s3 = s2; i3 = i2; s2 = s1; i2 = i1;                    \
            if (LESSI(dv, jv, s0, i0)) { s1 = s0; i1 = i0; s0 = (dv); i0 = (jv); } \
            else                       { s1 = (dv); i1 = (jv); }   \
        } else {                                                   \
            if (LESSI(dv, jv, s2, i2)) { s3 = s2; i3 = i2; s2 = (dv); i2 = (jv); } \
            else                       { s3 = (dv); i3 = (jv); }   \
        }                                                          \
    }

__global__ __launch_bounds__(BLOCK_THREADS)
void nn_pool_kernel(const float* __restrict__ obs1,
                    const float* __restrict__ obs2,
                    const float* __restrict__ W,
                    const float* __restrict__ b,
                    float* __restrict__ out,
                    int n)
{
    __shared__ __align__(16) float2 spos[NMAX];

    const int tid = threadIdx.x;

    // cooperative stage of positions into SMEM (vectorized float2 loads)
    const float2* __restrict__ gpos = (const float2*)obs2;
    for (int t = tid; t < n; t += BLOCK_THREADS)
        spos[t] = gpos[t];
    __syncthreads();

    const int warp = tid >> 5;
    const int lane = tid & 31;
    const int i = blockIdx.x * WARPS_PER_BLOCK + warp;
    if (i >= n) return;

    const float2 pi = spos[i];

    float s0 = CUDART_INF_F, s1 = CUDART_INF_F, s2 = CUDART_INF_F, s3 = CUDART_INF_F;
    int   i0 = n, i1 = n, i2 = n, i3 = n;

    // distance scan: each lane handles pairs (j, j+1), j = 2*lane + 64*t
    for (int j = 2 * lane; j < n; j += 64) {
        // 16B-aligned LDS.128: two consecutive float2 positions
        float4 p = *(const float4*)(&spos[j]);
        {
            float dx = p.x - pi.x;
            float dy = p.y - pi.y;
            float d2 = fmaf(dx, dx, dy * dy);
            if (j != i) { TRY_INSERT(d2, j); }
        }
        {
            int jj = j + 1;
            float dx = p.z - pi.x;
            float dy = p.w - pi.y;
            float d2 = fmaf(dx, dx, dy * dy);
            if (jj != i && jj < n) { TRY_INSERT(d2, jj); }
        }
    }

    // butterfly merge: after 5 steps every lane holds the warp-global top-4
    #pragma unroll
    for (int off = 16; off > 0; off >>= 1) {
        float t0 = __shfl_xor_sync(0xffffffffu, s0, off);
        float t1 = __shfl_xor_sync(0xffffffffu, s1, off);
        float t2 = __shfl_xor_sync(0xffffffffu, s2, off);
        float t3 = __shfl_xor_sync(0xffffffffu, s3, off);
        int   u0 = __shfl_xor_sync(0xffffffffu, i0, off);
        int   u1 = __shfl_xor_sync(0xffffffffu, i1, off);
        int   u2 = __shfl_xor_sync(0xffffffffu, i2, off);
        int   u3 = __shfl_xor_sync(0xffffffffu, i3, off);
        MERGE_INSERT(t0, u0);
        MERGE_INSERT(t1, u1);
        MERGE_INSERT(t2, u2);
        MERGE_INSERT(t3, u3);
    }

    // epilogue: lane = k*8 + e computes out[i][k*8 + e]
    // neighbor k (0..3 = nearest..4th), embedding channel e (0..7)
    const int k = lane >> 3;
    const int e = lane & 7;
    int nj = (k == 0) ? i0 : (k == 1) ? i1 : (k == 2) ? i2 : i3;

    const float2* __restrict__ go1 = (const float2*)obs1;
    float2 pj  = spos[nj];
    float2 o1j = go1[nj];
    float2 o1i = go1[i];

    // rel_pos = pos_j - pos_i ; rel_vel = (pos_j - obs1_j) - (pos_i - obs1_i)
    float rpx = pj.x - pi.x;
    float rpy = pj.y - pi.y;
    float rvx = (pj.x - o1j.x) - (pi.x - o1i.x);
    float rvy = (pj.y - o1j.y) - (pi.y - o1i.y);

    // h = relu([rpx, rpy, rvx, rvy] @ W[4,8] + b[8]) ; W row-major [in, out]
    float acc = b[e];
    acc = fmaf(rpx, W[0 * 8 + e], acc);
    acc = fmaf(rpy, W[1 * 8 + e], acc);
    acc = fmaf(rvx, W[2 * 8 + e], acc);
    acc = fmaf(rvy, W[3 * 8 + e], acc);

    out[i * 32 + lane] = fmaxf(acc, 0.0f);
}

extern "C" void kernel_launch(void* const* d_in, const int* in_sizes, int n_in,
                              void* d_out, int out_size) {
    const float* obs1 = (const float*)d_in[0];  // [N, 2]
    const float* obs2 = (const float*)d_in[1];  // [N, 2]
    const float* W    = (const float*)d_in[2];  // [4, 8]
    const float* b    = (const float*)d_in[3];  // [8]
    float* out = (float*)d_out;                  // [N, 32]

    int n = in_sizes[0] / 2;
    int blocks = (n + WARPS_PER_BLOCK - 1) / WARPS_PER_BLOCK;
    nn_pool_kernel<<<blocks, BLOCK_THREADS>>>(obs1, obs2, W, b, out, n);
}